// round 8
// baseline (speedup 1.0000x reference)
#include <cuda_runtime.h>

#define CH 6
#define MODES 16
#define BB 32
#define NPT 65536
#define NMASK 65535
#define TSTEPS 8

#define HALO7 28                 // 7 steps x halo 4
#define EXT 1032                 // smem window per block
#define CORE 976                 // EXT - 2*HALO7, valid output core [28,1004)
#define NBLK 68                  // ceil(NPT/CORE)
#define RKTHREADS 256
#define NREG 512                 // regions of 2 points; thread t owns regions t and t+256
#define EDG 516                  // per-channel stride in region-indexed edge arrays
#define FBLK 8                   // blocks per (b,i) in forward DFT

typedef unsigned long long ull;

// -------- scratch (no allocations allowed) --------
__device__ float  g_bufA[BB*CH*NPT];
__device__ float  g_part[BB*CH*FBLK*MODES*2];
__device__ float  g_Z[BB*CH*MODES*2];
__device__ float2 g_pack[CH*CH*3 + CH];    // staging for packed constants

__constant__ float  c_w[CH*CH*3];          // scalar weights (tail path)
__constant__ float  c_b[CH];
__constant__ float2 c_w2[CH*CH*3];         // duplicated (w,w)
__constant__ float2 c_b2[CH];              // duplicated (b,b)

__device__ __forceinline__ float htanh(float x){
    float y;
    asm("tanh.approx.f32 %0, %1;" : "=f"(y) : "f"(x));
    return y;
}
__device__ __forceinline__ ull pk2(float lo, float hi){
    ull r; asm("mov.b64 %0, {%1, %2};" : "=l"(r) : "f"(lo), "f"(hi)); return r;
}
__device__ __forceinline__ void upk2(ull v, float& lo, float& hi){
    asm("mov.b64 {%0, %1}, %2;" : "=f"(lo), "=f"(hi) : "l"(v));
}
__device__ __forceinline__ ull fma2(ull a, ull b, ull c){
    ull d; asm("fma.rn.f32x2 %0, %1, %2, %3;" : "=l"(d) : "l"(a), "l"(b), "l"(c)); return d;
}
__device__ __forceinline__ ull add2(ull a, ull b){
    ull d; asm("add.rn.f32x2 %0, %1, %2;" : "=l"(d) : "l"(a), "l"(b)); return d;
}

__global__ void init_pack_kernel(const float* __restrict__ conv_w,
                                 const float* __restrict__ conv_b){
    int i = threadIdx.x;
    if (i < CH*CH*3) g_pack[i] = make_float2(conv_w[i], conv_w[i]);
    if (i < CH)      g_pack[CH*CH*3 + i] = make_float2(conv_b[i], conv_b[i]);
}

// ---------------- fused 7-step RK4, paired-region f32x2 ----------------
// Regions r=0..511 own points (2r+1, 2r+2); thread t handles rA=t, rB=t+256.
// Packed lane layout: (A-value, B-value). kr2[ci] = {(kA1,kB1),(kA2,kB2)}.
// Edge arrays (region-indexed, double-buffered, stride-1):
//   eL[r] = k(2r)   : written by region r-1 owner (its k2); eL[0]=0 sentinel;
//                     eL[512]=k(1024) from t=255 (B).
//   eR[r] = k(2r+1) : written by region r owner (its k1); eR[512]=k(1025) from tail.
// Window for region r: w0=eL[r], w1=kr[0], w2=kr[1], w3=eR[r+1].
// Out-of-range masking at WRITE: tanh output zeroed for global pos >= NPT,
// so packed windows never need lane masks. u masked at smem load + update guard.
// Tail points [1025,1031) by tid<6 (scalar, runs after main block; reads OLD
// double-buffered edge arrays). Validity shrinks 4/side/step; core [28,1004).

template<int S>
__device__ __forceinline__ void stage(
    ull (&cu2)[CH][2],
    const float* __restrict__ eLr, const float* __restrict__ eRr,
    const float* __restrict__ ktr,
    float* __restrict__ eLw, float* __restrict__ eRw, float* __restrict__ ktw,
    const float* __restrict__ su,
    float cc, ull cc2, ull aw2, float aw,
    int gofs, int tid, bool edge,
    bool mA1, bool mA2, bool mB1, bool mB2,
    ull (&kr2)[CH][2], ull (&acc2)[CH][2], float (&acct)[CH])
{
    const int pA = 2*tid, pB = pA + 512;
    const ull* cw2 = (const ull*)c_w2;
    const ull* cb2 = (const ull*)c_b2;

    ull a2[CH][2];
    #pragma unroll
    for (int co=0; co<CH; co++){ a2[co][0]=0ull; a2[co][1]=0ull; }

    #pragma unroll
    for (int ci=0; ci<CH; ci++){
        ull w0, w1, w2, w3;
        if (S == 0){
            const float* ruA = su + ci*EXT + pA;
            const float* ruB = su + ci*EXT + pB;
            float2 a01 = *(const float2*)ruA;
            float2 a23 = *(const float2*)(ruA + 2);
            float2 b01 = *(const float2*)ruB;
            float2 b23 = *(const float2*)(ruB + 2);
            w0 = pk2(a01.x, b01.x);
            w1 = pk2(a01.y, b01.y);
            w2 = pk2(a23.x, b23.x);
            w3 = pk2(a23.y, b23.y);
        } else {
            float la = eLr[ci*EDG + tid];
            float lb = eLr[ci*EDG + tid + 256];
            float ra = eRr[ci*EDG + tid + 1];
            float rb = eRr[ci*EDG + tid + 257];
            w0 = pk2(la, lb);
            w1 = kr2[ci][0];
            w2 = kr2[ci][1];
            w3 = pk2(ra, rb);
        }
        #pragma unroll
        for (int co=0; co<CH; co++){
            const ull W0 = cw2[(co*CH+ci)*3 + 0];
            const ull W1 = cw2[(co*CH+ci)*3 + 1];
            const ull W2 = cw2[(co*CH+ci)*3 + 2];
            a2[co][0] = fma2(W0, w0, fma2(W1, w1, fma2(W2, w2, a2[co][0])));
            a2[co][1] = fma2(W0, w1, fma2(W1, w2, fma2(W2, w3, a2[co][1])));
        }
    }

    if (S == 0){
        #pragma unroll
        for (int co=0; co<CH; co++){ cu2[co][0]=a2[co][0]; cu2[co][1]=a2[co][1]; }
    } else {
        #pragma unroll
        for (int co=0; co<CH; co++){
            a2[co][0] = fma2(cc2, a2[co][0], cu2[co][0]);
            a2[co][1] = fma2(cc2, a2[co][1], cu2[co][1]);
        }
    }

    // tanh + write-side masking + edge stores
    #pragma unroll
    for (int co=0; co<CH; co++){
        ull ab0 = add2(a2[co][0], cb2[co]);
        ull ab1 = add2(a2[co][1], cb2[co]);
        float tA1,tB1,tA2,tB2;
        upk2(ab0, tA1, tB1);
        upk2(ab1, tA2, tB2);
        tA1 = htanh(tA1); tB1 = htanh(tB1);
        tA2 = htanh(tA2); tB2 = htanh(tB2);
        if (edge){
            tA1 = mA1 ? tA1 : 0.f;  tA2 = mA2 ? tA2 : 0.f;
            tB1 = mB1 ? tB1 : 0.f;  tB2 = mB2 ? tB2 : 0.f;
        }
        ull k0 = pk2(tA1, tB1);
        ull k1 = pk2(tA2, tB2);
        kr2[co][0] = k0;  kr2[co][1] = k1;
        acc2[co][0] = fma2(aw2, k0, acc2[co][0]);
        acc2[co][1] = fma2(aw2, k1, acc2[co][1]);
        if (S < 3){
            eRw[co*EDG + tid]       = tA1;   // k(2t+1)
            eRw[co*EDG + tid + 256] = tB1;   // k(2t+513)
            eLw[co*EDG + tid + 1]   = tA2;   // k(2t+2)
            eLw[co*EDG + tid + 257] = tB2;   // k(2t+514)
        }
    }

    // tail points p = 1025+tid for tid<6 (scalar; reads OLD buffers)
    if (tid < 6){
        const int p = 1025 + tid;
        float ttail[CH];
        #pragma unroll
        for (int co=0; co<CH; co++) ttail[co] = 0.f;
        #pragma unroll
        for (int ci=0; ci<CH; ci++){
            float vv[3];
            #pragma unroll
            for (int t3=0; t3<3; t3++){
                int pp = p - 1 + t3;                 // 1024..1031
                float v = su[ci*EXT + pp];
                if (S > 0){
                    float kv = (pp == 1024) ? eLr[ci*EDG + 512]
                                            : ktr[ci*8 + (pp - 1025)];
                    v = fmaf(cc, kv, v);
                }
                if ((unsigned)(gofs + pp) >= NPT) v = 0.f;
                vv[t3] = v;
            }
            #pragma unroll
            for (int co=0; co<CH; co++){
                const float w0 = c_w[(co*CH+ci)*3 + 0];
                const float w1 = c_w[(co*CH+ci)*3 + 1];
                const float w2 = c_w[(co*CH+ci)*3 + 2];
                ttail[co] = fmaf(w0, vv[0], fmaf(w1, vv[1], fmaf(w2, vv[2], ttail[co])));
            }
        }
        #pragma unroll
        for (int co=0; co<CH; co++){
            float t = htanh(ttail[co] + c_b[co]);
            if ((unsigned)(gofs + p) >= NPT) t = 0.f;
            if (S < 3){
                ktw[co*8 + tid] = t;
                if (tid == 0) eRw[co*EDG + 512] = t;   // k(1025)
            }
            if (tid < 3) acct[co] = fmaf(aw, t, acct[co]);
        }
    }
    if (S < 3) __syncthreads();
}

__global__ void __launch_bounds__(RKTHREADS, 2)
rk4_fused(const float* __restrict__ src, float* __restrict__ dst,
          const float* __restrict__ t_span)
{
    extern __shared__ float sm[];
    float* s_su = sm;                      // CH*EXT
    float* s_eL = s_su + CH*EXT;           // 2*CH*EDG
    float* s_eR = s_eL + 2*CH*EDG;         // 2*CH*EDG
    float* s_kt = s_eR + 2*CH*EDG;         // 2*CH*8
    float* s_ts = s_kt + 2*CH*8;           // TSTEPS

    const int b    = blockIdx.y;
    const int bx   = blockIdx.x;
    const int gofs = bx*CORE - HALO7;
    const int tid  = threadIdx.x;
    const bool edge = (bx == 0) | (bx == gridDim.x - 1);

    const int pA = 2*tid, pB = pA + 512;
    const bool mA1 = (unsigned)(gofs + pA + 1) < NPT;
    const bool mA2 = (unsigned)(gofs + pA + 2) < NPT;
    const bool mB1 = (unsigned)(gofs + pB + 1) < NPT;
    const bool mB2 = (unsigned)(gofs + pB + 2) < NPT;

    if (tid < CH){
        s_eL[tid*EDG + 0] = 0.f;  s_eL[(CH+tid)*EDG + 0] = 0.f;   // k(0) sentinels
        s_kt[tid*8 + 6] = 0.f;    s_kt[tid*8 + 7] = 0.f;          // k(1031+) sentinels
        s_kt[(CH+tid)*8 + 6] = 0.f; s_kt[(CH+tid)*8 + 7] = 0.f;
    }
    if (tid < TSTEPS) s_ts[tid] = t_span[tid];
    #pragma unroll
    for (int ch=0; ch<CH; ch++){
        const float* sc = src + ((size_t)b*CH + ch)*NPT;
        for (int p=tid; p<EXT; p+=RKTHREADS){
            int g = gofs + p;
            s_su[ch*EXT + p] = ((unsigned)g < NPT) ? sc[g] : 0.f;
        }
    }
    __syncthreads();

    float* eL0 = s_eL;  float* eL1 = s_eL + CH*EDG;
    float* eR0 = s_eR;  float* eR1 = s_eR + CH*EDG;
    float* kt0 = s_kt;  float* kt1 = s_kt + CH*8;

    const ull one2 = pk2(1.f, 1.f);
    const ull two2 = pk2(2.f, 2.f);

    #pragma unroll 1
    for (int s=0; s<TSTEPS-1; s++){
        const float dt  = s_ts[s+1] - s_ts[s];
        const float hdt = 0.5f*dt;
        const ull hdt2 = pk2(hdt, hdt);
        const ull dt2  = pk2(dt, dt);

        ull cu2[CH][2], kr2[CH][2], acc2[CH][2];
        float acct[CH];
        #pragma unroll
        for (int co=0; co<CH; co++){
            acct[co]=0.f; acc2[co][0]=0ull; acc2[co][1]=0ull;
        }

        stage<0>(cu2, eL0,eR0,kt0, eL0,eR0,kt0, s_su, 0.f, 0ull, one2, 1.f,
                 gofs, tid, edge, mA1,mA2,mB1,mB2, kr2, acc2, acct);
        stage<1>(cu2, eL0,eR0,kt0, eL1,eR1,kt1, s_su, hdt, hdt2, two2, 2.f,
                 gofs, tid, edge, mA1,mA2,mB1,mB2, kr2, acc2, acct);
        stage<2>(cu2, eL1,eR1,kt1, eL0,eR0,kt0, s_su, hdt, hdt2, two2, 2.f,
                 gofs, tid, edge, mA1,mA2,mB1,mB2, kr2, acc2, acct);
        stage<3>(cu2, eL0,eR0,kt0, eL1,eR1,kt1, s_su, dt,  dt2,  one2, 1.f,
                 gofs, tid, edge, mA1,mA2,mB1,mB2, kr2, acc2, acct);

        __syncthreads();            // stage-3 tail su reads complete

        const float dt6 = dt * (1.0f/6.0f);
        #pragma unroll
        for (int co=0; co<CH; co++){
            float aA1,aB1,aA2,aB2;
            upk2(acc2[co][0], aA1, aB1);
            upk2(acc2[co][1], aA2, aB2);
            float* rp = s_su + co*EXT;
            if (mA1) rp[pA+1] += dt6 * aA1;
            if (mA2) rp[pA+2] += dt6 * aA2;
            if (mB1) rp[pB+1] += dt6 * aB1;
            if (mB2) rp[pB+2] += dt6 * aB2;
        }
        if (tid < 3){
            int p = 1025 + tid;
            if ((unsigned)(gofs + p) < NPT){
                #pragma unroll
                for (int co=0; co<CH; co++)
                    s_su[co*EXT + p] += dt6 * acct[co];
            }
        }
        __syncthreads();            // updated su visible to next step
    }

    // final store: core [28, 1004)
    #pragma unroll
    for (int co=0; co<CH; co++){
        float* dp = dst + ((size_t)b*CH + co)*NPT;
        const float* rp = s_su + co*EXT;
        int pts[4] = {pA+1, pA+2, pB+1, pB+2};
        #pragma unroll
        for (int j=0; j<4; j++){
            int p = pts[j];
            int g = gofs + p;
            if (p >= HALO7 && p < EXT-HALO7 && (unsigned)g < NPT)
                dp[g] = rp[p];
        }
    }
}

// ---------------- forward 16-mode DFT (partial sums) ----------------
__global__ void __launch_bounds__(256)
fwd_dft_kernel(const float* __restrict__ u)
{
    const int blk  = blockIdx.x;                 // [0, BB*CH*FBLK)
    const int seg  = blk & (FBLK-1);
    const int bi   = blk / FBLK;                 // b*CH + i
    const int tid  = threadIdx.x;
    const int lane = tid & 31, warp = tid >> 5;
    const int n0   = seg*8192 + warp*1024 + lane;  // stride-32 walk, coalesced
    const float* x = u + (size_t)bi*NPT;

    const float TWO_PI = 6.283185307179586f;
    float cr[MODES], cim[MODES], ck[MODES], sk[MODES], dc[MODES], ds[MODES];
    #pragma unroll
    for (int k=0; k<MODES; k++){
        cr[k]=0.f; cim[k]=0.f;
        float a0 = TWO_PI * ((float)((k*n0) & NMASK) * (1.0f/NPT));
        sincosf(a0, &sk[k], &ck[k]);
        float ad = TWO_PI * ((float)(k*32) * (1.0f/NPT));
        sincosf(ad, &ds[k], &dc[k]);
    }
    #pragma unroll 2
    for (int j=0; j<32; j++){
        float v = __ldg(&x[n0 + (j<<5)]);
        #pragma unroll
        for (int k=0; k<MODES; k++){
            cr[k]  = fmaf( v, ck[k], cr[k]);     // X += u * e^{-i theta}
            cim[k] = fmaf(-v, sk[k], cim[k]);
            float nc = ck[k]*dc[k] - sk[k]*ds[k];
            sk[k] = fmaf(ck[k], ds[k], sk[k]*dc[k]);
            ck[k] = nc;
        }
    }
    #pragma unroll
    for (int k=0; k<MODES; k++){
        #pragma unroll
        for (int off=16; off; off>>=1){
            cr[k]  += __shfl_xor_sync(0xffffffffu, cr[k],  off);
            cim[k] += __shfl_xor_sync(0xffffffffu, cim[k], off);
        }
    }
    __shared__ float red[8][MODES*2];
    if (lane == 0){
        #pragma unroll
        for (int k=0; k<MODES; k++){
            red[warp][2*k]   = cr[k];
            red[warp][2*k+1] = cim[k];
        }
    }
    __syncthreads();
    if (tid < MODES*2){
        float s = 0.f;
        #pragma unroll
        for (int w=0; w<8; w++) s += red[w][tid];
        g_part[(bi*FBLK + seg)*(MODES*2) + tid] = s;
    }
}

// ---------------- mix: reduce partials, fold proj into mode weights ----------------
__global__ void mix_kernel(const float* __restrict__ sw_r, const float* __restrict__ sw_i,
                           const float* __restrict__ proj_w)
{
    const int b = blockIdx.x;
    const int t = threadIdx.x;         // 96 = CH*MODES
    const int o = t / MODES, k = t % MODES;
    float Zr = 0.f, Zi = 0.f;
    #pragma unroll
    for (int i=0; i<CH; i++){
        float Xr=0.f, Xi=0.f;
        int bi = b*CH + i;
        #pragma unroll
        for (int s=0; s<FBLK; s++){
            Xr += g_part[(bi*FBLK+s)*(MODES*2) + 2*k];
            Xi += g_part[(bi*FBLK+s)*(MODES*2) + 2*k + 1];
        }
        float Wr=0.f, Wi=0.f;
        #pragma unroll
        for (int c=0; c<CH; c++){
            float pw = proj_w[o*CH + c];
            Wr = fmaf(sw_r[(i*CH+c)*MODES + k], pw, Wr);
            Wi = fmaf(sw_i[(i*CH+c)*MODES + k], pw, Wi);
        }
        Zr += Xr*Wr - Xi*Wi;
        Zi += Xr*Wi + Xi*Wr;
    }
    float scale = (k==0) ? (1.0f/NPT) : (2.0f/NPT);   // irfft: DC once, others doubled
    g_Z[(b*CH+o)*MODES*2 + 2*k]     = Zr*scale;
    g_Z[(b*CH+o)*MODES*2 + 2*k + 1] = Zi*scale;
}

// ---------------- synthesis: 16-mode irfft + bias ----------------
__global__ void __launch_bounds__(256)
synth_kernel(float* __restrict__ out, const float* __restrict__ proj_b)
{
    const int blk  = blockIdx.x;        // b*8 + seg
    const int b    = blk >> 3, seg = blk & 7;
    const int tid  = threadIdx.x, lane = tid & 31, warp = tid >> 5;
    const int n0   = seg*8192 + warp*1024 + lane;

    __shared__ float zz[CH*MODES*2];
    __shared__ float pb[CH];
    if (tid < CH*MODES*2) zz[tid] = g_Z[b*CH*MODES*2 + tid];
    if (tid < CH)         pb[tid] = proj_b[tid];
    __syncthreads();

    const float TWO_PI = 6.283185307179586f;
    float ck[MODES], sk[MODES], dc[MODES], ds[MODES];
    #pragma unroll
    for (int k=0; k<MODES; k++){
        float a0 = TWO_PI * ((float)((k*n0) & NMASK) * (1.0f/NPT));
        sincosf(a0, &sk[k], &ck[k]);
        float ad = TWO_PI * ((float)(k*32) * (1.0f/NPT));
        sincosf(ad, &ds[k], &dc[k]);
    }
    for (int j=0; j<32; j++){
        int n = n0 + (j<<5);
        float accv[CH];
        #pragma unroll
        for (int o=0; o<CH; o++) accv[o] = pb[o];
        #pragma unroll
        for (int k=0; k<MODES; k++){
            float c = ck[k], s = sk[k];
            #pragma unroll
            for (int o=0; o<CH; o++){
                accv[o] = fmaf( zz[(o*MODES+k)*2],     c, accv[o]);
                accv[o] = fmaf(-zz[(o*MODES+k)*2 + 1], s, accv[o]);
            }
            float nc = c*dc[k] - s*ds[k];
            sk[k] = fmaf(c, ds[k], s*dc[k]);
            ck[k] = nc;
        }
        #pragma unroll
        for (int o=0; o<CH; o++)
            out[((size_t)(b*CH + o))*NPT + n] = accv[o];
    }
}

// ---------------- launch ----------------
extern "C" void kernel_launch(void* const* d_in, const int* in_sizes, int n_in,
                              void* d_out, int out_size)
{
    const float* u0     = (const float*)d_in[0];
    const float* t_span = (const float*)d_in[1];
    const float* conv_w = (const float*)d_in[2];
    const float* conv_b = (const float*)d_in[3];
    const float* sw_r   = (const float*)d_in[4];
    const float* sw_i   = (const float*)d_in[5];
    const float* proj_w = (const float*)d_in[6];
    const float* proj_b = (const float*)d_in[7];
    float* out = (float*)d_out;

    float*  bufA  = nullptr;
    float2* packp = nullptr;
    cudaGetSymbolAddress((void**)&bufA, g_bufA);
    cudaGetSymbolAddress((void**)&packp, g_pack);

    cudaMemcpyToSymbolAsync(c_w, conv_w, CH*CH*3*sizeof(float), 0,
                            cudaMemcpyDeviceToDevice, 0);
    cudaMemcpyToSymbolAsync(c_b, conv_b, CH*sizeof(float), 0,
                            cudaMemcpyDeviceToDevice, 0);
    init_pack_kernel<<<1, 128>>>(conv_w, conv_b);
    cudaMemcpyToSymbolAsync(c_w2, packp, CH*CH*3*sizeof(float2), 0,
                            cudaMemcpyDeviceToDevice, 0);
    cudaMemcpyToSymbolAsync(c_b2, packp + CH*CH*3, CH*sizeof(float2), 0,
                            cudaMemcpyDeviceToDevice, 0);

    const int rk_smem = (CH*EXT + 4*CH*EDG + 4*CH*8 + TSTEPS) * sizeof(float);
    cudaFuncSetAttribute(rk4_fused, cudaFuncAttributeMaxDynamicSharedMemorySize, rk_smem);

    dim3 rkgrid(NBLK, BB);
    rk4_fused<<<rkgrid, RKTHREADS, rk_smem>>>(u0, bufA, t_span);

    fwd_dft_kernel<<<BB*CH*FBLK, 256>>>(bufA);
    mix_kernel<<<BB, CH*MODES>>>(sw_r, sw_i, proj_w);
    synth_kernel<<<BB*8, 256>>>(out, proj_b);
}

// round 9
// speedup vs baseline: 2.5155x; 2.5155x over previous
#include <cuda_runtime.h>

#define CH 6
#define MODES 16
#define BB 32
#define NPT 65536
#define NMASK 65535
#define TSTEPS 8

#define EXT 1026                 // logical window: indices 0..1025
#define SROW 1032                // padded row stride (float4 alignment)
#define VMARG 29                 // validity margin after 28 stage-shrinks (+1 end)
#define CORE 968                 // EXT - 2*VMARG, valid output core [29, 997)
#define NBLK 68                  // 68*968 = 65824 >= NPT
#define RKTHREADS 256            // 4 points/thread tile [1,1025) exactly
#define EDG 260                  // per-channel stride in edge arrays
#define FBLK 8                   // blocks per (b,i) in forward DFT

// -------- scratch (no allocations allowed) --------
__device__ float g_bufA[BB*CH*NPT];
__device__ float g_part[BB*CH*FBLK*MODES*2];
__device__ float g_Z[BB*CH*MODES*2];

__constant__ float c_w[CH*CH*3];   // [co][ci][3]
__constant__ float c_b[CH];

__device__ __forceinline__ float htanh(float x){
    float y;
    asm("tanh.approx.f32 %0, %1;" : "=f"(y) : "f"(x));
    return y;
}

// ---------------- stage ----------------
// 4 points/thread: own p0+1..p0+4 (p0=4*tid), window [p0, p0+5]; threads tile
// [1,1025) exactly — NO tail. Linearity split: cu = conv(u)+bias (stage 0);
// stages 1-3: a = cu + cc*conv(k). Edge arrays (double-buffered, stride-1):
//   eL[i] = k(4i)   (i=0 sentinel=0; thread t writes i=t+1 <- kr[3])
//   eR[i] = k(4i+1) (thread t writes i=t <- kr[0]; i=256 sentinel=0)
// Sentinel zeros fall inside the shrinking validity margin by design.
// Stages 1-3 read ONLY edges/kr (not su) -> su update needs no pre-barrier.

template<int S>
__device__ __forceinline__ void stage(
    float (&cu)[CH][4],
    const float* __restrict__ eLr, const float* __restrict__ eRr,
    float* __restrict__ eLw, float* __restrict__ eRw,
    const float* __restrict__ su,
    float cc, float aw, int gofs, int tid, bool edge,
    float (&kr)[CH][4], float (&acc)[CH][4])
{
    const int p0 = 4*tid;
    float a[CH][4];
    #pragma unroll
    for (int co=0; co<CH; co++){ a[co][0]=0.f; a[co][1]=0.f; a[co][2]=0.f; a[co][3]=0.f; }

    if (S == 0){
        #pragma unroll
        for (int ci=0; ci<CH; ci++){
            const float* ru = su + ci*SROW + p0;
            float4 u0 = *(const float4*)ru;          // p0..p0+3 (aligned)
            float2 u1 = *(const float2*)(ru + 4);    // p0+4, p0+5
            float xv[6] = {u0.x, u0.y, u0.z, u0.w, u1.x, u1.y};
            #pragma unroll
            for (int co=0; co<CH; co++){
                const float w0 = c_w[(co*CH+ci)*3 + 0];
                const float w1 = c_w[(co*CH+ci)*3 + 1];
                const float w2 = c_w[(co*CH+ci)*3 + 2];
                #pragma unroll
                for (int j=0; j<4; j++)
                    a[co][j] = fmaf(w0, xv[j], fmaf(w1, xv[j+1], fmaf(w2, xv[j+2], a[co][j])));
            }
        }
        // fold bias into cu
        #pragma unroll
        for (int co=0; co<CH; co++){
            const float bias = c_b[co];
            #pragma unroll
            for (int j=0; j<4; j++){
                a[co][j] += bias;
                cu[co][j] = a[co][j];
            }
        }
    } else {
        // hoisted, batched edge loads (MLP)
        float xl[CH], xr[CH];
        #pragma unroll
        for (int ci=0; ci<CH; ci++){
            xl[ci] = eLr[ci*EDG + tid];
            xr[ci] = eRr[ci*EDG + tid + 1];
        }
        #pragma unroll
        for (int ci=0; ci<CH; ci++){
            float xvk[6];
            xvk[0] = xl[ci];
            xvk[1] = kr[ci][0]; xvk[2] = kr[ci][1];
            xvk[3] = kr[ci][2]; xvk[4] = kr[ci][3];
            xvk[5] = xr[ci];
            if (edge){
                #pragma unroll
                for (int j=0; j<6; j++)
                    if ((unsigned)(gofs + p0 + j) >= NPT) xvk[j] = 0.f;
            }
            #pragma unroll
            for (int co=0; co<CH; co++){
                const float w0 = c_w[(co*CH+ci)*3 + 0];
                const float w1 = c_w[(co*CH+ci)*3 + 1];
                const float w2 = c_w[(co*CH+ci)*3 + 2];
                #pragma unroll
                for (int j=0; j<4; j++)
                    a[co][j] = fmaf(w0, xvk[j], fmaf(w1, xvk[j+1], fmaf(w2, xvk[j+2], a[co][j])));
            }
        }
        #pragma unroll
        for (int co=0; co<CH; co++)
            #pragma unroll
            for (int j=0; j<4; j++) a[co][j] = fmaf(cc, a[co][j], cu[co][j]);
    }

    #pragma unroll
    for (int co=0; co<CH; co++){
        #pragma unroll
        for (int j=0; j<4; j++){
            float t = htanh(a[co][j]);
            kr[co][j] = t;
            acc[co][j] = fmaf(aw, t, acc[co][j]);
        }
        if (S < 3){
            eLw[co*EDG + tid + 1] = kr[co][3];   // k(4t+4)
            eRw[co*EDG + tid]     = kr[co][0];   // k(4t+1)
        }
    }
    if (S < 3) __syncthreads();
}

// ---------------- fused 7-step RK4 kernel ----------------
__global__ void __launch_bounds__(RKTHREADS, 2)
rk4_fused(const float* __restrict__ src, float* __restrict__ dst,
          const float* __restrict__ t_span)
{
    extern __shared__ float sm[];
    float* s_su = sm;                      // CH*SROW
    float* s_eL = s_su + CH*SROW;          // 2*CH*EDG
    float* s_eR = s_eL + 2*CH*EDG;         // 2*CH*EDG
    float* s_ts = s_eR + 2*CH*EDG;         // TSTEPS

    const int b    = blockIdx.y;
    const int bx   = blockIdx.x;
    const int gofs = bx*CORE - VMARG;
    const int tid  = threadIdx.x;
    const bool edge = (bx == 0) | (bx == gridDim.x - 1);
    const int p0 = 4*tid;

    if (tid < CH){
        s_eL[tid*EDG + 0] = 0.f;           // k(0) sentinels, both buffers
        s_eL[(CH+tid)*EDG + 0] = 0.f;
        s_eR[tid*EDG + 256] = 0.f;         // k(1025) sentinels, both buffers
        s_eR[(CH+tid)*EDG + 256] = 0.f;
    }
    if (tid < TSTEPS) s_ts[tid] = t_span[tid];
    #pragma unroll
    for (int ch=0; ch<CH; ch++){
        const float* sc = src + ((size_t)b*CH + ch)*NPT;
        for (int p=tid; p<EXT; p+=RKTHREADS){
            int g = gofs + p;
            s_su[ch*SROW + p] = ((unsigned)g < NPT) ? sc[g] : 0.f;
        }
    }
    __syncthreads();

    float* eL0 = s_eL;  float* eL1 = s_eL + CH*EDG;
    float* eR0 = s_eR;  float* eR1 = s_eR + CH*EDG;

    #pragma unroll 1
    for (int s=0; s<TSTEPS-1; s++){
        const float dt  = s_ts[s+1] - s_ts[s];
        const float hdt = 0.5f*dt;

        float cu[CH][4], kr[CH][4], acc[CH][4];
        #pragma unroll
        for (int co=0; co<CH; co++){
            acc[co][0]=0.f; acc[co][1]=0.f; acc[co][2]=0.f; acc[co][3]=0.f;
        }

        stage<0>(cu, eL0,eR0, eL0,eR0, s_su, 0.f, 1.f, gofs, tid, edge, kr, acc);
        stage<1>(cu, eL0,eR0, eL1,eR1, s_su, hdt, 2.f, gofs, tid, edge, kr, acc);
        stage<2>(cu, eL1,eR1, eL0,eR0, s_su, hdt, 2.f, gofs, tid, edge, kr, acc);
        stage<3>(cu, eL0,eR0, eL1,eR1, s_su, dt,  1.f, gofs, tid, edge, kr, acc);

        // su update fused into stage-3 epilogue (stages 1-3 never read su,
        // and stage-0 window reads of this step are long since barriered)
        const float dt6 = dt * (1.0f/6.0f);
        #pragma unroll
        for (int co=0; co<CH; co++){
            float* rp = s_su + co*SROW;
            #pragma unroll
            for (int j=0; j<4; j++){
                int p = p0 + 1 + j;
                int g = gofs + p;
                if (!edge || (unsigned)g < NPT)
                    rp[p] += dt6 * acc[co][j];
            }
        }
        __syncthreads();            // updated su visible to next step's stage 0
    }

    // final store: valid core [29, 997)
    #pragma unroll
    for (int co=0; co<CH; co++){
        float* dp = dst + ((size_t)b*CH + co)*NPT;
        const float* rp = s_su + co*SROW;
        #pragma unroll
        for (int j=0; j<4; j++){
            int p = p0 + 1 + j;
            int g = gofs + p;
            if (p >= VMARG && p < EXT-VMARG && (unsigned)g < NPT)
                dp[g] = rp[p];
        }
    }
}

// ---------------- forward 16-mode DFT (partial sums) ----------------
__global__ void __launch_bounds__(256)
fwd_dft_kernel(const float* __restrict__ u)
{
    const int blk  = blockIdx.x;                 // [0, BB*CH*FBLK)
    const int seg  = blk & (FBLK-1);
    const int bi   = blk / FBLK;                 // b*CH + i
    const int tid  = threadIdx.x;
    const int lane = tid & 31, warp = tid >> 5;
    const int n0   = seg*8192 + warp*1024 + lane;  // stride-32 walk, coalesced
    const float* x = u + (size_t)bi*NPT;

    const float TWO_PI = 6.283185307179586f;
    float cr[MODES], cim[MODES], ck[MODES], sk[MODES], dc[MODES], ds[MODES];
    #pragma unroll
    for (int k=0; k<MODES; k++){
        cr[k]=0.f; cim[k]=0.f;
        float a0 = TWO_PI * ((float)((k*n0) & NMASK) * (1.0f/NPT));
        sincosf(a0, &sk[k], &ck[k]);
        float ad = TWO_PI * ((float)(k*32) * (1.0f/NPT));
        sincosf(ad, &ds[k], &dc[k]);
    }
    #pragma unroll 2
    for (int j=0; j<32; j++){
        float v = __ldg(&x[n0 + (j<<5)]);
        #pragma unroll
        for (int k=0; k<MODES; k++){
            cr[k]  = fmaf( v, ck[k], cr[k]);     // X += u * e^{-i theta}
            cim[k] = fmaf(-v, sk[k], cim[k]);
            float nc = ck[k]*dc[k] - sk[k]*ds[k];
            sk[k] = fmaf(ck[k], ds[k], sk[k]*dc[k]);
            ck[k] = nc;
        }
    }
    #pragma unroll
    for (int k=0; k<MODES; k++){
        #pragma unroll
        for (int off=16; off; off>>=1){
            cr[k]  += __shfl_xor_sync(0xffffffffu, cr[k],  off);
            cim[k] += __shfl_xor_sync(0xffffffffu, cim[k], off);
        }
    }
    __shared__ float red[8][MODES*2];
    if (lane == 0){
        #pragma unroll
        for (int k=0; k<MODES; k++){
            red[warp][2*k]   = cr[k];
            red[warp][2*k+1] = cim[k];
        }
    }
    __syncthreads();
    if (tid < MODES*2){
        float s = 0.f;
        #pragma unroll
        for (int w=0; w<8; w++) s += red[w][tid];
        g_part[(bi*FBLK + seg)*(MODES*2) + tid] = s;
    }
}

// ---------------- mix: reduce partials, fold proj into mode weights ----------------
__global__ void mix_kernel(const float* __restrict__ sw_r, const float* __restrict__ sw_i,
                           const float* __restrict__ proj_w)
{
    const int b = blockIdx.x;
    const int t = threadIdx.x;         // 96 = CH*MODES
    const int o = t / MODES, k = t % MODES;
    float Zr = 0.f, Zi = 0.f;
    #pragma unroll
    for (int i=0; i<CH; i++){
        float Xr=0.f, Xi=0.f;
        int bi = b*CH + i;
        #pragma unroll
        for (int s=0; s<FBLK; s++){
            Xr += g_part[(bi*FBLK+s)*(MODES*2) + 2*k];
            Xi += g_part[(bi*FBLK+s)*(MODES*2) + 2*k + 1];
        }
        float Wr=0.f, Wi=0.f;
        #pragma unroll
        for (int c=0; c<CH; c++){
            float pw = proj_w[o*CH + c];
            Wr = fmaf(sw_r[(i*CH+c)*MODES + k], pw, Wr);
            Wi = fmaf(sw_i[(i*CH+c)*MODES + k], pw, Wi);
        }
        Zr += Xr*Wr - Xi*Wi;
        Zi += Xr*Wi + Xi*Wr;
    }
    float scale = (k==0) ? (1.0f/NPT) : (2.0f/NPT);   // irfft: DC once, others doubled
    g_Z[(b*CH+o)*MODES*2 + 2*k]     = Zr*scale;
    g_Z[(b*CH+o)*MODES*2 + 2*k + 1] = Zi*scale;
}

// ---------------- synthesis: 16-mode irfft + bias ----------------
__global__ void __launch_bounds__(256)
synth_kernel(float* __restrict__ out, const float* __restrict__ proj_b)
{
    const int blk  = blockIdx.x;        // b*8 + seg
    const int b    = blk >> 3, seg = blk & 7;
    const int tid  = threadIdx.x, lane = tid & 31, warp = tid >> 5;
    const int n0   = seg*8192 + warp*1024 + lane;

    __shared__ float zz[CH*MODES*2];
    __shared__ float pb[CH];
    if (tid < CH*MODES*2) zz[tid] = g_Z[b*CH*MODES*2 + tid];
    if (tid < CH)         pb[tid] = proj_b[tid];
    __syncthreads();

    const float TWO_PI = 6.283185307179586f;
    float ck[MODES], sk[MODES], dc[MODES], ds[MODES];
    #pragma unroll
    for (int k=0; k<MODES; k++){
        float a0 = TWO_PI * ((float)((k*n0) & NMASK) * (1.0f/NPT));
        sincosf(a0, &sk[k], &ck[k]);
        float ad = TWO_PI * ((float)(k*32) * (1.0f/NPT));
        sincosf(ad, &ds[k], &dc[k]);
    }
    for (int j=0; j<32; j++){
        int n = n0 + (j<<5);
        float accv[CH];
        #pragma unroll
        for (int o=0; o<CH; o++) accv[o] = pb[o];
        #pragma unroll
        for (int k=0; k<MODES; k++){
            float c = ck[k], s = sk[k];
            #pragma unroll
            for (int o=0; o<CH; o++){
                accv[o] = fmaf( zz[(o*MODES+k)*2],     c, accv[o]);
                accv[o] = fmaf(-zz[(o*MODES+k)*2 + 1], s, accv[o]);
            }
            float nc = c*dc[k] - s*ds[k];
            sk[k] = fmaf(c, ds[k], s*dc[k]);
            ck[k] = nc;
        }
        #pragma unroll
        for (int o=0; o<CH; o++)
            out[((size_t)(b*CH + o))*NPT + n] = accv[o];
    }
}

// ---------------- launch ----------------
extern "C" void kernel_launch(void* const* d_in, const int* in_sizes, int n_in,
                              void* d_out, int out_size)
{
    const float* u0     = (const float*)d_in[0];
    const float* t_span = (const float*)d_in[1];
    const float* conv_w = (const float*)d_in[2];
    const float* conv_b = (const float*)d_in[3];
    const float* sw_r   = (const float*)d_in[4];
    const float* sw_i   = (const float*)d_in[5];
    const float* proj_w = (const float*)d_in[6];
    const float* proj_b = (const float*)d_in[7];
    float* out = (float*)d_out;

    float* bufA = nullptr;
    cudaGetSymbolAddress((void**)&bufA, g_bufA);

    cudaMemcpyToSymbolAsync(c_w, conv_w, CH*CH*3*sizeof(float), 0,
                            cudaMemcpyDeviceToDevice, 0);
    cudaMemcpyToSymbolAsync(c_b, conv_b, CH*sizeof(float), 0,
                            cudaMemcpyDeviceToDevice, 0);

    const int rk_smem = (CH*SROW + 4*CH*EDG + TSTEPS) * sizeof(float);
    cudaFuncSetAttribute(rk4_fused, cudaFuncAttributeMaxDynamicSharedMemorySize, rk_smem);

    dim3 rkgrid(NBLK, BB);
    rk4_fused<<<rkgrid, RKTHREADS, rk_smem>>>(u0, bufA, t_span);

    fwd_dft_kernel<<<BB*CH*FBLK, 256>>>(bufA);
    mix_kernel<<<BB, CH*MODES>>>(sw_r, sw_i, proj_w);
    synth_kernel<<<BB*8, 256>>>(out, proj_b);
}